// round 16
// baseline (speedup 1.0000x reference)
#include <cuda_runtime.h>
#include <cuda_bf16.h>
#include <mma.h>
#include <float.h>
#include <cstdint>

using namespace nvcuda;

#define BQ    4096
#define POOL  1024
#define DIM   768
#define TOPK  5
#define TOPC  8
#define PLEN  5
#define NOUT  ((size_t)BQ * TOPK * PLEN * DIM)   // 78,643,200

// -------- device scratch (v16) --------
__device__ float g16_qn[(size_t)BQ * DIM];
__device__ float g16_kn[(size_t)POOL * DIM];
__device__ float g16_dist[(size_t)BQ * POOL];
__device__ int   g16_cand[BQ * TOPC];
__device__ int   g16_topi[BQ * TOPK];
__device__ float g16_rowloss[BQ];

// ============================================================
// Fused normalize: denominators via the BITWISE-v13 sequential
// fp32 fadd(fmul) chain (32 owner threads, smem-transposed
// coalesced loads), then all 256 threads divide (L2-hot re-read).
// ============================================================
__global__ __launch_bounds__(256) void normalize_v16(const float* __restrict__ src,
                                                     float* __restrict__ dst) {
    __shared__ float tile[32][33];
    __shared__ float sdenom[32];
    const int rowBase = blockIdx.x * 32;
    const int tid = threadIdx.x;
    float sum = 0.f;
    for (int c0 = 0; c0 < DIM; c0 += 32) {
        #pragma unroll
        for (int e = tid; e < 1024; e += 256) {
            int r = e >> 5, c = e & 31;
            tile[r][c] = src[(size_t)(rowBase + r) * DIM + c0 + c];
        }
        __syncthreads();
        if (tid < 32) {
            #pragma unroll
            for (int j = 0; j < 32; j++) {
                float v = tile[tid][j];
                sum = __fadd_rn(sum, __fmul_rn(v, v));   // exact v13/v11 order
            }
        }
        __syncthreads();
    }
    if (tid < 32) sdenom[tid] = fmaxf(sqrtf(sum), 1e-12f);
    __syncthreads();
    // coalesced divide: consecutive tid -> consecutive columns
    for (int e = tid; e < 32 * DIM; e += 256) {
        int r = e / DIM, c = e - r * DIM;
        size_t g = (size_t)(rowBase + r) * DIM + c;
        dst[g] = __fdiv_rn(src[g], sdenom[r]);
    }
}

// ============================================================
// Coarse tf32 GEMM v16: 128(M)x256(N) block tile, K-chunk 16,
// 2-stage cp.async, dynamic smem. 8 warps (2x4), 64x64 per warp.
// Coarse-only output -> accumulation order free.
// ============================================================
#define LDS16 20   // 16 + 4 pad floats

__device__ __forceinline__ void cpa16_v16(unsigned int dst, const float* src) {
    asm volatile("cp.async.ca.shared.global [%0], [%1], 16;" :: "r"(dst), "l"(src));
}

__global__ __launch_bounds__(256) void gemm_tf32_v16() {
    extern __shared__ float smem16[];
    float* As[2] = { smem16,                 smem16 + 128 * LDS16 };
    float* Bs[2] = { smem16 + 256 * LDS16,   smem16 + 256 * LDS16 + 256 * LDS16 };

    const int tid = threadIdx.x;
    const int wid = tid >> 5;
    const int wm  = wid & 1;          // 0..1 -> 64 M-rows each
    const int wn  = wid >> 1;         // 0..3 -> 64 N-cols each
    const float* Ag = g16_qn + (size_t)blockIdx.y * 128 * DIM;
    const float* Bg = g16_kn + (size_t)blockIdx.x * 256 * DIM;

    wmma::fragment<wmma::accumulator, 16, 16, 8, float> c[4][4];
    #pragma unroll
    for (int i = 0; i < 4; i++)
        #pragma unroll
        for (int j = 0; j < 4; j++) wmma::fill_fragment(c[i][j], 0.0f);

    const int lr = tid >> 2;          // 0..63
    const int lc = tid & 3;           // 0..3

    auto load_stage = [&](int s, int kt) {
        #pragma unroll
        for (int h = 0; h < 2; h++) {   // A: 128 rows
            int row = lr + h * 64;
            unsigned int da = (unsigned int)__cvta_generic_to_shared(&As[s][row * LDS16 + lc * 4]);
            cpa16_v16(da, Ag + (size_t)row * DIM + kt + lc * 4);
        }
        #pragma unroll
        for (int h = 0; h < 4; h++) {   // B: 256 rows
            int row = lr + h * 64;
            unsigned int db = (unsigned int)__cvta_generic_to_shared(&Bs[s][row * LDS16 + lc * 4]);
            cpa16_v16(db, Bg + (size_t)row * DIM + kt + lc * 4);
        }
        asm volatile("cp.async.commit_group;");
    };

    load_stage(0, 0);

    const int NIT = DIM / 16;   // 48
    for (int it = 0; it < NIT; it++) {
        const int cur = it & 1;
        if (it + 1 < NIT) load_stage((it + 1) & 1, (it + 1) * 16);

        if (it + 1 < NIT) asm volatile("cp.async.wait_group 1;");
        else              asm volatile("cp.async.wait_group 0;");
        __syncthreads();

        #pragma unroll
        for (int ks = 0; ks < 16; ks += 8) {
            wmma::fragment<wmma::matrix_a, 16, 16, 8, wmma::precision::tf32, wmma::row_major> a[4];
            wmma::fragment<wmma::matrix_b, 16, 16, 8, wmma::precision::tf32, wmma::col_major> b[4];
            #pragma unroll
            for (int i = 0; i < 4; i++) {
                wmma::load_matrix_sync(a[i], &As[cur][(wm * 64 + i * 16) * LDS16 + ks], LDS16);
                #pragma unroll
                for (int t = 0; t < a[i].num_elements; t++)
                    a[i].x[t] = wmma::__float_to_tf32(a[i].x[t]);
            }
            #pragma unroll
            for (int j = 0; j < 4; j++) {
                wmma::load_matrix_sync(b[j], &Bs[cur][(wn * 64 + j * 16) * LDS16 + ks], LDS16);
                #pragma unroll
                for (int t = 0; t < b[j].num_elements; t++)
                    b[j].x[t] = wmma::__float_to_tf32(b[j].x[t]);
            }
            #pragma unroll
            for (int i = 0; i < 4; i++)
                #pragma unroll
                for (int j = 0; j < 4; j++)
                    wmma::mma_sync(c[i][j], a[i], b[j], c[i][j]);
        }
        __syncthreads();
    }

    #pragma unroll
    for (int i = 0; i < 4; i++)
        #pragma unroll
        for (int j = 0; j < 4; j++) {
            int row0 = blockIdx.y * 128 + wm * 64 + i * 16;
            int col0 = blockIdx.x * 256 + wn * 64 + j * 16;
            wmma::store_matrix_sync(g16_dist + (size_t)row0 * POOL + col0,
                                    c[i][j], POOL, wmma::mem_row_major);
        }
}

#define GEMM16_SMEM ((128 + 128 + 256 + 256) * LDS16 * (int)sizeof(float))  // 61,440 B

// ============================================================
// Coarse top-8 per row — verbatim v15. Warp per row.
// ============================================================
__global__ __launch_bounds__(256) void topk_v16() {
    const int warp = threadIdx.x >> 5;
    const int lane = threadIdx.x & 31;
    const int row  = blockIdx.x * 8 + warp;
    const float* drow = g16_dist + (size_t)row * POOL;

    float vals[32];
    #pragma unroll
    for (int j = 0; j < 32; j++) vals[j] = drow[j * 32 + lane];

    for (int it = 0; it < TOPC; it++) {
        float bv = -FLT_MAX; int bi = 0x7fffffff;
        #pragma unroll
        for (int j = 0; j < 32; j++) {
            int gi = j * 32 + lane;
            if (vals[j] > bv || (vals[j] == bv && gi < bi)) { bv = vals[j]; bi = gi; }
        }
        #pragma unroll
        for (int o = 16; o; o >>= 1) {
            float ov = __shfl_xor_sync(0xffffffffu, bv, o);
            int   oi = __shfl_xor_sync(0xffffffffu, bi, o);
            if (ov > bv || (ov == bv && oi < bi)) { bv = ov; bi = oi; }
        }
        if (lane == 0) g16_cand[row * TOPC + it] = bi;
        if ((bi & 31) == lane) {
            int jw = bi >> 5;
            #pragma unroll
            for (int j = 0; j < 32; j++) if (j == jw) vals[j] = -FLT_MAX;
        }
    }
}

// ============================================================
// Exact rescore + dedup — verbatim v15 (q staged in smem).
// ============================================================
__device__ __forceinline__ void df_acc16(float& hi, float& lo, float p, float pe) {
    float s = hi + p;
    float bb = s - hi;
    float err = (hi - (s - bb)) + (p - bb);
    err += lo + pe;
    hi = s + err;
    lo = err - (hi - s);
}

__global__ __launch_bounds__(256) void rescore_v16() {
    const int row  = blockIdx.x;
    const int warp = threadIdx.x >> 5;
    const int lane = threadIdx.x & 31;
    const int cand = g16_cand[row * TOPC + warp];

    __shared__ float qs[DIM];
    for (int i = threadIdx.x; i < DIM; i += 256) qs[i] = g16_qn[(size_t)row * DIM + i];
    __syncthreads();

    const float* k = g16_kn + (size_t)cand * DIM;

    float hi = 0.f, lo = 0.f;
    #pragma unroll
    for (int j = 0; j < DIM / 32; j++) {
        float a = qs[j * 32 + lane];
        float b = k[j * 32 + lane];
        float p  = a * b;
        float pe = fmaf(a, b, -p);
        df_acc16(hi, lo, p, pe);
    }
    #pragma unroll
    for (int o = 16; o; o >>= 1) {
        float ohi = __shfl_xor_sync(0xffffffffu, hi, o);
        float olo = __shfl_xor_sync(0xffffffffu, lo, o);
        df_acc16(hi, lo, ohi, olo);
    }

    __shared__ double sv[TOPC];
    __shared__ int    si[TOPC];
    if (lane == 0) { sv[warp] = (double)hi + (double)lo; si[warp] = cand; }
    __syncthreads();

    if (threadIdx.x == 0) {
        double lv[TOPC]; int li[TOPC];
        #pragma unroll
        for (int a = 0; a < TOPC; a++) { lv[a] = sv[a]; li[a] = si[a]; }

        // dedup: keep first occurrence of each index
        #pragma unroll
        for (int a = 1; a < TOPC; a++) {
            #pragma unroll
            for (int b2 = 0; b2 < TOPC; b2++) {
                if (b2 < a && li[b2] == li[a]) lv[a] = -1e300;
            }
        }

        // full selection sort of 8: desc value, ties -> asc index
        #pragma unroll
        for (int a = 0; a < TOPC - 1; a++) {
            int best = a;
            #pragma unroll
            for (int b2 = 0; b2 < TOPC; b2++) {
                if (b2 <= a) continue;
                if (lv[b2] > lv[best] || (lv[b2] == lv[best] && li[b2] < li[best])) best = b2;
            }
            double tv = lv[best]; int ti = li[best];
            lv[best] = lv[a]; li[best] = li[a];
            lv[a] = tv; li[a] = ti;
        }

        float l = 0.f;
        #pragma unroll
        for (int a = 0; a < TOPK; a++) {
            g16_topi[row * TOPK + a] = li[a];
            l += fabsf((float)lv[a]);
        }
        g16_rowloss[row] = l;
    }
}

// ============================================================
// Gather — verbatim v15.
// ============================================================
__global__ __launch_bounds__(256) void gather_v16(const float* __restrict__ pv,
                                                  float* __restrict__ out) {
    const int bk = blockIdx.x;
    const int idx = g16_topi[bk];
    const float4* src = (const float4*)(pv  + (size_t)idx * PLEN * DIM);
    float4*       dst = (float4*)      (out + (size_t)bk  * PLEN * DIM);
    const int n4 = PLEN * DIM / 4;               // 960
    for (int i = threadIdx.x; i < n4; i += 256) dst[i] = src[i];
}

// ============================================================
__global__ __launch_bounds__(1024) void loss_v16(float* __restrict__ out) {
    __shared__ float red[32];
    float s = 0.f;
    for (int i = threadIdx.x; i < BQ; i += 1024) s += g16_rowloss[i];
    #pragma unroll
    for (int o = 16; o; o >>= 1) s += __shfl_xor_sync(0xffffffffu, s, o);
    if ((threadIdx.x & 31) == 0) red[threadIdx.x >> 5] = s;
    __syncthreads();
    if (threadIdx.x < 32) {
        float v = red[threadIdx.x];
        #pragma unroll
        for (int o = 16; o; o >>= 1) v += __shfl_xor_sync(0xffffffffu, v, o);
        if (threadIdx.x == 0) out[0] = v / (float)BQ;
    }
}

// ============================================================
extern "C" void kernel_launch(void* const* d_in, const int* in_sizes, int n_in,
                              void* d_out, int out_size) {
    const float* query = (const float*)d_in[0];   // [4096, 768]
    const float* pkeys = (const float*)d_in[1];   // [1024, 768]
    const float* pvals = (const float*)d_in[2];   // [1024, 5, 768]
    float* out = (float*)d_out;

    float *qn_ptr, *kn_ptr;
    cudaGetSymbolAddress((void**)&qn_ptr, g16_qn);
    cudaGetSymbolAddress((void**)&kn_ptr, g16_kn);

    static int smem_set = 0;
    if (!smem_set) {
        cudaFuncSetAttribute(gemm_tf32_v16,
                             cudaFuncAttributeMaxDynamicSharedMemorySize, GEMM16_SMEM);
        smem_set = 1;
    }

    normalize_v16<<<POOL / 32, 256>>>(pkeys, kn_ptr);
    normalize_v16<<<BQ   / 32, 256>>>(query, qn_ptr);

    dim3 gemm_grid(POOL / 256, BQ / 128);   // (4, 32)
    gemm_tf32_v16<<<gemm_grid, 256, GEMM16_SMEM>>>();

    topk_v16<<<BQ / 8, 256>>>();

    rescore_v16<<<BQ, 256>>>();

    gather_v16<<<BQ * TOPK, 256>>>(pvals, out);

    if ((size_t)out_size > NOUT)
        loss_v16<<<1, 1024>>>(out + NOUT);
}